// round 9
// baseline (speedup 1.0000x reference)
#include <cuda_runtime.h>

#define TPB  512
#define ROWS 64
#define XSTR 148   // mult of 4: 16B-aligned k-quads; rg*148 mod 32 distinct banks
#define SSTR 51

typedef unsigned long long ull;

// ---- embedding-region offsets inside smem (floats) ----
enum {
  EO_SUIT = 0, EO_RANK = 40, EO_POS = 152, EO_ACTION = 208, EO_ACTIVE = 304,
  EO_STREET = 320, EO_NUMP = 360, EO_BLIND = 416, EO_SW = 432, EO_SB = 480,
  EO_TOTAL = 528
};

__constant__ int c_seg_base[31] = {
  EO_STREET, EO_POS,
  EO_ACTIVE, EO_ACTIVE, EO_ACTIVE, EO_ACTIVE, EO_ACTIVE,
  EO_POS, EO_POS, EO_POS, EO_POS, EO_POS,
  -1, -3, -4, -6,
  EO_POS, EO_ACTION, EO_BLIND,
  -2,
  EO_ACTION, EO_POS, EO_BLIND,
  EO_NUMP, EO_POS,
  -5, -5, -5, -5, -5, -5
};
__constant__ int c_seg_col[31] = {
  18, 20,
  22, 23, 24, 25, 26,
  27, 28, 29, 30, 31,
  40, 41, 42, 43,
  35, 36, 37,
  39,
  32, 33, 34,
  19, 38,
  44, 45, 46, 47, 48, 49
};

struct Params {
  const float* state;
  const float* suit_emb; const float* rank_emb;
  const float *hW1, *hb1, *hW2, *hb2, *hW3, *hb3;
  const float *bW1, *bb1, *bW2, *bb2, *bW3, *bb3;
  const float *cW1, *cb1, *cW2, *cb2, *cW3, *cb3;
  const float *pos_emb, *action_emb, *active_emb, *street_emb, *nump_emb, *blind_emb;
  const float *scalar_W, *scalar_b;
  float* out;
  int nrows;
};

#define CP_COMMIT() asm volatile("cp.async.commit_group;" ::: "memory")
#define CP_WAIT0()  asm volatile("cp.async.wait_group 0;"  ::: "memory")

__device__ __forceinline__ void cp_f(float* dst, const float* __restrict__ src, int n, int tid) {
  for (int e = tid; e < n; e += TPB) dst[e] = src[e];
}

// Async transpose-scatter: W[KC,NN] (row-major global) -> W_T[c*SS + k] smem.
template<int KC, int NN, int SS>
__device__ __forceinline__ void stageWT(float* WT, const float* __restrict__ W, int tid) {
  unsigned base = (unsigned)__cvta_generic_to_shared(WT);
  for (int e = tid; e < KC * NN; e += TPB) {
    int k = e / NN, c = e - k * NN;
    unsigned dst = base + (unsigned)((c * SS + k) << 2);
    asm volatile("cp.async.ca.shared.global [%0], [%1], 4;" :: "r"(dst), "l"(W + e) : "memory");
  }
}
template<int NN>
__device__ __forceinline__ void stageBv(float* Bb, const float* __restrict__ b, int tid) {
  unsigned base = (unsigned)__cvta_generic_to_shared(Bb);
  for (int e = tid; e < NN; e += TPB) {
    unsigned dst = base + (unsigned)(e << 2);
    asm volatile("cp.async.ca.shared.global [%0], [%1], 4;" :: "r"(dst), "l"(b + e) : "memory");
  }
}

// Y[64,N] = X[64,K] @ W[K,N] + b (store cols < NSTORE), optional leaky.
// 16 warps; warp tile = 8 rows x 32 cols. Lane: rg=lane&3 (rows i*4+rg, i<2),
// cg=lane>>2 (cols j*8+cg, j<4). k processed in QUADS via 16B LDS:
// ulonglong2 = {f32x2(k,k+1), f32x2(k+2,k+3)}; both halves FFMA2 into the same
// packed acc; (lo+hi) reduced once in epilogue. W transposed, slice stride S=K+4.
template<int K, int S, int CT, int NSTORE, bool LEAKY>
__device__ __forceinline__ void gemm_tile(const float* __restrict__ Xs, float* __restrict__ Ys,
                                          const float* __restrict__ Wt, const float* __restrict__ Bs,
                                          int tid)
{
  const int wid  = tid >> 5;
  const int lane = tid & 31;
  const int rg   = lane & 3;
  const int cg   = lane >> 2;

  for (int t = wid; t < 8 * CT; t += 16) {
    const int rt = t & 7;
    const int ct = t >> 3;
    const float* xb = Xs + (rt * 8 + rg) * XSTR;
    const float* wb = Wt + (ct * 32 + cg) * S;

    ull acc[2][4];
#pragma unroll
    for (int i = 0; i < 2; ++i)
#pragma unroll
      for (int j = 0; j < 4; ++j) acc[i][j] = 0ull;

#pragma unroll 2
    for (int kk = 0; kk < K; kk += 4) {
      ulonglong2 xv[2], wv[4];
#pragma unroll
      for (int i = 0; i < 2; ++i)
        xv[i] = *reinterpret_cast<const ulonglong2*>(xb + i * 4 * XSTR + kk);
#pragma unroll
      for (int j = 0; j < 4; ++j)
        wv[j] = *reinterpret_cast<const ulonglong2*>(wb + j * 8 * S + kk);
#pragma unroll
      for (int i = 0; i < 2; ++i)
#pragma unroll
        for (int j = 0; j < 4; ++j) {
          asm("fma.rn.f32x2 %0, %1, %2, %3;"
              : "=l"(acc[i][j]) : "l"(wv[j].x), "l"(xv[i].x), "l"(acc[i][j]));
          asm("fma.rn.f32x2 %0, %1, %2, %3;"
              : "=l"(acc[i][j]) : "l"(wv[j].y), "l"(xv[i].y), "l"(acc[i][j]));
        }
    }

#pragma unroll
    for (int i = 0; i < 2; ++i) {
      const int r = rt * 8 + i * 4 + rg;
#pragma unroll
      for (int j = 0; j < 4; ++j) {
        const int c = ct * 32 + j * 8 + cg;
        float lo, hi;
        asm("mov.b64 {%0, %1}, %2;" : "=f"(lo), "=f"(hi) : "l"(acc[i][j]));
        float v = lo + hi + Bs[c];
        if (LEAKY) v = fmaxf(v, 0.01f * v);
        if (c < NSTORE) Ys[r * XSTR + c] = v;
      }
    }
  }
}

__global__ void __launch_bounds__(TPB, 1)
PreProcess_kernel(Params p)
{
  extern __shared__ float sm[];
  float* stateS = sm;                      // 3264
  float* X      = stateS + ROWS * SSTR;    // 64*148 = 9472
  float* Y      = X + ROWS * XSTR;         // 9472
  float* WA     = Y + ROWS * XSTR;         // 23680 (cW1: reads up to col 159 x S=148)
  float* BA     = WA + 23680;              // 160
  float* WB     = BA + 160;                // 9472 (max of 96x84, 64x148)
  float* BB     = WB + 9472;               // 96
  float* embS   = BB + 96;                 // 528
  // total 56144 floats = 224576 B

  const int tid  = threadIdx.x;
  const int row0 = blockIdx.x * ROWS;

  // ---- async-stage first weights; meanwhile load state tile + tables ----
  stageWT<64, 64, 68>(WA, p.hW1, tid); stageBv<64>(BA, p.hb1, tid); CP_COMMIT();

  for (int e = tid; e < ROWS * 50; e += TPB) {
    int r = e / 50, c = e - r * 50;
    float v = 0.f;
    if (row0 + r < p.nrows) v = p.state[(size_t)(row0 + r) * 50 + c];
    stateS[r * SSTR + c] = v;
  }
  cp_f(embS + EO_SUIT,   p.suit_emb,   40, tid);
  cp_f(embS + EO_RANK,   p.rank_emb,  112, tid);
  cp_f(embS + EO_POS,    p.pos_emb,    56, tid);
  cp_f(embS + EO_ACTION, p.action_emb, 96, tid);
  cp_f(embS + EO_ACTIVE, p.active_emb, 16, tid);
  cp_f(embS + EO_STREET, p.street_emb, 40, tid);
  cp_f(embS + EO_NUMP,   p.nump_emb,   56, tid);
  cp_f(embS + EO_BLIND,  p.blind_emb,  16, tid);
  cp_f(embS + EO_SW,     p.scalar_W,   48, tid);
  cp_f(embS + EO_SB,     p.scalar_b,   48, tid);
  __syncthreads();

  // ---- build card inputs: X[:,0:64]=hand, X[:,64:144]=board ----
  for (int e = tid; e < ROWS * 144; e += TPB) {
    int r = e / 144, c = e - r * 144;
    int card = c >> 4, t = c & 15;
    float v;
    if (t < 8) {
      int s = (int)stateS[r * SSTR + 2 * card + 1];
      v = embS[EO_SUIT + s * 8 + t];
    } else {
      int rk = (int)stateS[r * SSTR + 2 * card];
      v = embS[EO_RANK + rk * 8 + (t - 8)];
    }
    X[r * XSTR + c] = v;
  }
  CP_WAIT0();
  __syncthreads();

  // ---- 9 layers; stage L+1 into the idle W buffer during gemm(L) ----
  stageWT<80, 80, 84>(WB, p.bW1, tid); stageBv<80>(BB, p.bb1, tid); CP_COMMIT();
  gemm_tile<64, 68, 2, 64, true >(X, Y, WA, BA, tid);
  CP_WAIT0(); __syncthreads();

  stageWT<64, 64, 68>(WA, p.hW2, tid); stageBv<64>(BA, p.hb2, tid); CP_COMMIT();
  gemm_tile<80, 84, 3, 80, true >(X + 64, Y + 64, WB, BB, tid);
  CP_WAIT0(); __syncthreads();

  stageWT<80, 80, 84>(WB, p.bW2, tid); stageBv<80>(BB, p.bb2, tid); CP_COMMIT();
  gemm_tile<64, 68, 2, 64, true >(Y, X, WA, BA, tid);
  CP_WAIT0(); __syncthreads();

  stageWT<64, 64, 68>(WA, p.hW3, tid); stageBv<64>(BA, p.hb3, tid); CP_COMMIT();
  gemm_tile<80, 84, 3, 80, true >(Y + 64, X + 64, WB, BB, tid);
  CP_WAIT0(); __syncthreads();

  stageWT<80, 80, 84>(WB, p.bW3, tid); stageBv<80>(BB, p.bb3, tid); CP_COMMIT();
  gemm_tile<64, 68, 2, 64, false>(X, Y, WA, BA, tid);
  CP_WAIT0(); __syncthreads();

  stageWT<144, 144, 148>(WA, p.cW1, tid); stageBv<144>(BA, p.cb1, tid); CP_COMMIT();
  gemm_tile<80, 84, 3, 80, false>(X + 64, Y + 64, WB, BB, tid);
  CP_WAIT0(); __syncthreads();

  stageWT<144, 64, 148>(WB, p.cW2, tid); stageBv<64>(BB, p.cb2, tid); CP_COMMIT();
  gemm_tile<144, 148, 5, 144, true >(Y, X, WA, BA, tid);  // hb L1 (concat = Y[:,0:144])
  CP_WAIT0(); __syncthreads();

  stageWT<64, 64, 68>(WA, p.cW3, tid); stageBv<64>(BA, p.cb3, tid); CP_COMMIT();
  gemm_tile<144, 148, 2, 64, true >(X, Y, WB, BB, tid);
  CP_WAIT0(); __syncthreads();

  gemm_tile<64, 68, 2, 64, false>(Y, X, WA, BA, tid);
  __syncthreads();
  // final hand_board in X[:,0:64]

  // ---- assemble 312-float output rows (coalesced) ----
  size_t obase = (size_t)row0 * 312;
  for (int e = tid; e < ROWS * 312; e += TPB) {
    int r = e / 312, c = e - r * 312;
    if (row0 + r >= p.nrows) continue;
    float v;
    if (c < 64) {
      v = X[r * XSTR + c];
    } else {
      int s = (c - 64) >> 3, j = (c - 64) & 7;
      int base = c_seg_base[s];
      float sv = stateS[r * SSTR + c_seg_col[s]];
      if (base >= 0) {
        int idx = (int)sv;
        v = embS[base + idx * 8 + j];
      } else {
        int w = -base - 1;
        v = fmaf(sv, embS[EO_SW + w * 8 + j], embS[EO_SB + w * 8 + j]);
      }
    }
    p.out[obase + e] = v;
  }
}

extern "C" void kernel_launch(void* const* d_in, const int* in_sizes, int n_in,
                              void* d_out, int out_size)
{
  Params p;
  p.state      = (const float*)d_in[0];
  p.suit_emb   = (const float*)d_in[1];
  p.rank_emb   = (const float*)d_in[2];
  p.hW1 = (const float*)d_in[3];  p.hb1 = (const float*)d_in[4];
  p.hW2 = (const float*)d_in[5];  p.hb2 = (const float*)d_in[6];
  p.hW3 = (const float*)d_in[7];  p.hb3 = (const float*)d_in[8];
  p.bW1 = (const float*)d_in[9];  p.bb1 = (const float*)d_in[10];
  p.bW2 = (const float*)d_in[11]; p.bb2 = (const float*)d_in[12];
  p.bW3 = (const float*)d_in[13]; p.bb3 = (const float*)d_in[14];
  p.cW1 = (const float*)d_in[15]; p.cb1 = (const float*)d_in[16];
  p.cW2 = (const float*)d_in[17]; p.cb2 = (const float*)d_in[18];
  p.cW3 = (const float*)d_in[19]; p.cb3 = (const float*)d_in[20];
  p.pos_emb    = (const float*)d_in[21];
  p.action_emb = (const float*)d_in[22];
  p.active_emb = (const float*)d_in[23];
  p.street_emb = (const float*)d_in[24];
  p.nump_emb   = (const float*)d_in[25];
  p.blind_emb  = (const float*)d_in[26];
  p.scalar_W   = (const float*)d_in[27];
  p.scalar_b   = (const float*)d_in[28];
  p.out   = (float*)d_out;
  p.nrows = in_sizes[0] / 50;

  const int smem_floats = ROWS * SSTR + 2 * ROWS * XSTR
                        + 23680 + 160 + 9472 + 96 + EO_TOTAL;
  const int smem_bytes = smem_floats * (int)sizeof(float);
  cudaFuncSetAttribute(PreProcess_kernel,
                       cudaFuncAttributeMaxDynamicSharedMemorySize, smem_bytes);

  int grid = (p.nrows + ROWS - 1) / ROWS;
  PreProcess_kernel<<<grid, TPB, smem_bytes>>>(p);
}